// round 17
// baseline (speedup 1.0000x reference)
#include <cuda_runtime.h>
#include <cstdint>
#include <cstddef>

#define VIN  4096      // 16^3
#define VOUT 262144    // 64^3
#define PADP 36        // float2 row stride for paired x/w tables
#define STGW 40        // staging row stride in floats

// ---------------- device scratch (no allocation allowed) ----------------
__device__ float g_P1[512];   // partial sums: [nc*4+q]
__device__ float g_P2[512];
__device__ unsigned int g_cnt;                 // zero-init; wraps mod 512 each launch
__device__ __align__(16) uint4 g_Frag[1024];   // [ks][mt][lane] A-fragments (tf32 bits)
__device__ float g_B[128];    // [n][o] fused bias
__device__ float g_rstd[2];

// ---------------- helpers ----------------
__device__ __forceinline__ uint32_t tf32_rna(float v) {
    uint32_t r;
    asm("cvt.rna.tf32.f32 %0, %1;" : "=r"(r) : "f"(v));
    return r;
}
__device__ __forceinline__ void mma_tf32(float* c, const uint32_t* a, uint32_t b0, uint32_t b1) {
    asm volatile(
        "mma.sync.aligned.m16n8k8.row.col.f32.tf32.tf32.f32 "
        "{%0,%1,%2,%3}, {%4,%5,%6,%7}, {%8,%9}, {%0,%1,%2,%3};"
        : "+f"(c[0]), "+f"(c[1]), "+f"(c[2]), "+f"(c[3])
        : "r"(a[0]), "r"(a[1]), "r"(a[2]), "r"(a[3]), "r"(b0), "r"(b1));
}
__device__ __forceinline__ void stcs1(float* p, float v) {
    asm volatile("st.global.cs.f32 [%0], %1;" :: "l"(p), "f"(v) : "memory");
}

// ---------------- kernel 1: fused stats + prep (last-block-done) ----------------
__global__ void __launch_bounds__(256)
k_pre(const float* __restrict__ x,
      const float* __restrict__ w_ct,
      const float* __restrict__ b_ct,
      const float* __restrict__ gamma,
      const float* __restrict__ beta,
      const float* __restrict__ w_pw) {
    const int tid = threadIdx.x;

    // ---- phase 1: per-(n,c,quarter) partial sums ----
    {
        const int b = blockIdx.x;          // nc*4 + q
        const float4* p = (const float4*)(x + (size_t)b * 1024);
        float4 v = p[tid];
        float a1 = v.x + v.y + v.z + v.w;
        float a2 = v.x * v.x + v.y * v.y + v.z * v.z + v.w * v.w;
#pragma unroll
        for (int off = 16; off; off >>= 1) {
            a1 += __shfl_xor_sync(0xffffffffu, a1, off);
            a2 += __shfl_xor_sync(0xffffffffu, a2, off);
        }
        __shared__ float s1[8], s2[8];
        int wid = tid >> 5, lid = tid & 31;
        if (lid == 0) { s1[wid] = a1; s2[wid] = a2; }
        __syncthreads();
        if (tid == 0) {
            float t1 = 0.f, t2 = 0.f;
#pragma unroll
            for (int w = 0; w < 8; ++w) { t1 += s1[w]; t2 += s2[w]; }
            g_P1[b] = t1;
            g_P2[b] = t2;
        }
    }
    __threadfence();
    __shared__ int isLast;
    if (tid == 0)
        isLast = (atomicInc(&g_cnt, 511u) == 511u);
    __syncthreads();
    if (!isLast) return;

    // ---- phase 2: closed-form stats + fragment-ordered tf32 weights ----
    __shared__ double dS1[128], dS2[128];
    __shared__ float sMean[2], sRstd[2];

    if (tid < 128) {
        const int c = tid & 63;
        float s1 = 0.f, s2 = 0.f;
#pragma unroll 4
        for (int t = 0; t < 64; ++t) {
            float w = w_ct[c * 64 + t];
            s1 += w;
            s2 += w * w;
        }
        float X1 = g_P1[tid * 4] + g_P1[tid * 4 + 1] + g_P1[tid * 4 + 2] + g_P1[tid * 4 + 3];
        float X2 = g_P2[tid * 4] + g_P2[tid * 4 + 1] + g_P2[tid * 4 + 2] + g_P2[tid * 4 + 3];
        double bb = (double)b_ct[c];
        double S1 = (double)s1, S2 = (double)s2;
        dS1[tid] = S1 * (double)X1 + (double)VOUT * bb;
        dS2[tid] = S2 * (double)X2 + 2.0 * bb * S1 * (double)X1 + (double)VOUT * bb * bb;
    }
    __syncthreads();
#pragma unroll
    for (int st = 32; st > 0; st >>= 1) {
        if ((tid & 63) < st && tid < 128) {
            dS1[tid] += dS1[tid + st];
            dS2[tid] += dS2[tid + st];
        }
        __syncthreads();
    }
    if (tid < 2) {
        double sy = dS1[tid * 64], sy2 = dS2[tid * 64];
        double mean = sy / 16777216.0;
        double var  = sy2 / 16777216.0 - mean * mean;
        double rstd = 1.0 / sqrt(var + 1e-5);
        sMean[tid] = (float)mean;
        sRstd[tid] = (float)rstd;
        g_rstd[tid] = (float)rstd;
    }
    __syncthreads();

    // Fragment-ordered A: g_Frag[ks*4+mt][lane] = {Wg[o0][c0], Wg[o1][c0], Wg[o0][c1], Wg[o1][c1]}
    for (int idx = tid; idx < 1024; idx += 256) {
        const int ks = idx >> 7;
        const int mt = (idx >> 5) & 3;
        const int l = idx & 31;
        const int lq = l >> 2, lr = l & 3;
        const int o0 = mt * 16 + lq, o1 = o0 + 8;
        const int c0 = ks * 8 + lr, c1 = c0 + 4;
        uint4 f;
        f.x = tf32_rna(w_pw[o0 * 64 + c0] * gamma[c0]);
        f.y = tf32_rna(w_pw[o1 * 64 + c0] * gamma[c0]);
        f.z = tf32_rna(w_pw[o0 * 64 + c1] * gamma[c1]);
        f.w = tf32_rna(w_pw[o1 * 64 + c1] * gamma[c1]);
        g_Frag[idx] = f;
    }

    if (tid < 128) {
        int n = tid >> 6, o = tid & 63;
        float mean = sMean[n], rstd = sRstd[n];
        float acc1 = 0.f, acc2 = 0.f;
#pragma unroll 4
        for (int c = 0; c < 64; ++c) {
            float wpc = w_pw[o * 64 + c];
            acc1 += wpc * gamma[c] * (b_ct[c] - mean);
            acc2 += wpc * beta[c];
        }
        g_B[tid] = rstd * acc1 + acc2;
    }
}

// ---------------- kernel 2: tf32 HMMA scatter-GEMM, 32o x 128s warp tiles ----------------
// Block = (n, dout, h): 64 o x 256 s.  Warp = (ohalf = warp>>1, shalf = warp&1).
// Warp owns o in [ohalf*32, +32), s in [shalf*128, +128).
// s = shalf*128 + nt*8 + lq;  j = s>>6 = shalf*2 + (nt>>3);  k = lq&3;
// w_in = 2*(nt&7) + (lq>>2).
// z[c][s] = w_ct[c, i, j, k] * x[n, c, d, h, w_in]
// out[n, o, dout, 4h + j, s&63] = rstd * D + B[n][o]
__global__ void __launch_bounds__(128, 2)
k_main(const float* __restrict__ x,
       const float* __restrict__ w_ct,
       float* __restrict__ out) {
    __shared__ __align__(16) uint4 sFrag[1024];           // A fragments, 16 KB
    __shared__ __align__(16) float2 sXp[16 * PADP];       // [w_in][pair p]: (x[c], x[c+4])
    __shared__ __align__(16) float2 sWp[16 * PADP];       // [jk][pair p]
    __shared__ __align__(16) float sStage[4 * 16 * STGW]; // per-warp staging
    __shared__ float sB[64];

    const int tid = threadIdx.x;
    const int warp = tid >> 5;
    const int l = tid & 31;
    const int lq = l >> 2, lr = l & 3;
    const int ohalf = warp >> 1, shalf = warp & 1;

    const int b = blockIdx.x;
    const int n = b >> 10;
    const int dout = (b >> 4) & 63;
    const int h = b & 15;
    const int d = dout >> 2, i = dout & 3;

    // ---- stage operands ----
    {
#pragma unroll
        for (int t = 0; t < 8; ++t)
            sFrag[tid + t * 128] = g_Frag[tid + t * 128];
        float* xp = (float*)sXp;
        float* wp = (float*)sWp;
#pragma unroll
        for (int idx = tid; idx < 256; idx += 128) {
            const int c = idx >> 2, q = idx & 3;
            const int p2 = ((c >> 3) * 4 + (c & 3)) * 2 + ((c >> 2) & 1);
            float4 xv = *(const float4*)(x + (size_t)(n * 64 + c) * VIN + d * 256 + h * 16 + q * 4);
            xp[(q * 4 + 0) * (2 * PADP) + p2] = xv.x;
            xp[(q * 4 + 1) * (2 * PADP) + p2] = xv.y;
            xp[(q * 4 + 2) * (2 * PADP) + p2] = xv.z;
            xp[(q * 4 + 3) * (2 * PADP) + p2] = xv.w;
            float4 wv = *(const float4*)(w_ct + c * 64 + i * 16 + q * 4);
            wp[(q * 4 + 0) * (2 * PADP) + p2] = wv.x;
            wp[(q * 4 + 1) * (2 * PADP) + p2] = wv.y;
            wp[(q * 4 + 2) * (2 * PADP) + p2] = wv.z;
            wp[(q * 4 + 3) * (2 * PADP) + p2] = wv.w;
        }
        if (tid < 64) sB[tid] = g_B[n * 64 + tid];
    }
    __syncthreads();

    const float rstd = g_rstd[n];
    const int xrhi = lq >> 2;                 // 0/1

    float acc[2][16][4];
#pragma unroll
    for (int mt = 0; mt < 2; ++mt)
#pragma unroll
        for (int nt = 0; nt < 16; ++nt)
#pragma unroll
            for (int r = 0; r < 4; ++r) acc[mt][nt][r] = 0.f;

#pragma unroll
    for (int ks = 0; ks < 8; ++ks) {
        uint4 aV[2];
#pragma unroll
        for (int mt = 0; mt < 2; ++mt)
            aV[mt] = sFrag[(ks * 4 + ohalf * 2 + mt) * 32 + l];
        const int p = ks * 4 + lr;
        float2 wv[2];
#pragma unroll
        for (int j2 = 0; j2 < 2; ++j2)
            wv[j2] = sWp[((shalf * 2 + j2) * 4 + (lq & 3)) * PADP + p];
        float2 xv[8];
#pragma unroll
        for (int r = 0; r < 8; ++r)
            xv[r] = sXp[(2 * r + xrhi) * PADP + p];
#pragma unroll
        for (int nt = 0; nt < 16; ++nt) {
            const int j2 = nt >> 3, r = nt & 7;
            uint32_t b0 = tf32_rna(xv[r].x * wv[j2].x);
            uint32_t b1 = tf32_rna(xv[r].y * wv[j2].y);
            mma_tf32(acc[0][nt], (const uint32_t*)&aV[0], b0, b1);
            mma_tf32(acc[1][nt], (const uint32_t*)&aV[1], b0, b1);
        }
    }

    // ---- epilogue: per-warp smem-staged transpose -> coalesced streaming stores ----
    const size_t outBase = (size_t)n * 64 * VOUT + (size_t)dout * 4096 + (size_t)h * 256;
    float* stg = sStage + warp * (16 * STGW);

#pragma unroll
    for (int mt = 0; mt < 2; ++mt) {
        const int obase = ohalf * 32 + mt * 16;
        const int o0 = obase + lq;
        const int o1 = o0 + 8;
        const float B0 = sB[o0], B1 = sB[o1];
#pragma unroll
        for (int hh = 0; hh < 4; ++hh) {
#pragma unroll
            for (int t = 0; t < 4; ++t) {
                const int nt = hh * 4 + t;
                const int sl = t * 8 + 2 * lr;
                float2 v0, v1;
                v0.x = fmaf(rstd, acc[mt][nt][0], B0);
                v0.y = fmaf(rstd, acc[mt][nt][1], B0);
                v1.x = fmaf(rstd, acc[mt][nt][2], B1);
                v1.y = fmaf(rstd, acc[mt][nt][3], B1);
                *(float2*)&stg[lq * STGW + sl] = v0;
                *(float2*)&stg[(lq + 8) * STGW + sl] = v1;
            }
            __syncwarp();
            // global s for lane l in this chunk: s = shalf*128 + hh*32 + l
            const int soff = (shalf * 2 + (hh >> 1)) * 64 + (hh & 1) * 32 + l;
#pragma unroll
            for (int r = 0; r < 16; ++r) {
                float v = stg[r * STGW + l];
                const int o = obase + r;
                stcs1(out + outBase + (size_t)o * VOUT + soff, v);
            }
            __syncwarp();
        }
    }
}

extern "C" void kernel_launch(void* const* d_in, const int* in_sizes, int n_in,
                              void* d_out, int out_size) {
    (void)in_sizes; (void)n_in; (void)out_size;
    const float* x     = (const float*)d_in[0];
    const float* w_ct  = (const float*)d_in[1];
    const float* b_ct  = (const float*)d_in[2];
    const float* gamma = (const float*)d_in[3];
    const float* beta  = (const float*)d_in[4];
    const float* w_pw  = (const float*)d_in[5];
    float* out = (float*)d_out;

    k_pre<<<512, 256>>>(x, w_ct, b_ct, gamma, beta, w_pw);
    k_main<<<2048, 128>>>(x, w_ct, out);
}